// round 3
// baseline (speedup 1.0000x reference)
#include <cuda_runtime.h>
#include <cuda_bf16.h>
#include <cstdint>

// Problem shape (fixed by the dataset): N=M=4096, DIM=8, TASKS=8
constexpr int NN   = 4096;
constexpr int MM   = 4096;
constexpr int DIMC = 8;
constexpr int TT   = 8;

constexpr int TR = 32;    // rows per group (== warp size)
constexpr int TC = 128;   // columns per tile
constexpr int TILE_STRIDE = 132;            // padded smem stride (write-phase conflict-free)
constexpr int XT_STRIDE   = 33;             // transposed-x stride (conflict-free reads)
constexpr int MAXG = 136;                   // >= floor(4096/32) + (TASKS-1) = 135

// Scratch (no cudaMalloc allowed)
__device__ int   g_perm[MAXG * TR];   // row indices grouped by task, -1 = pad
__device__ int   g_gtask[MAXG];       // task id per group, -1 = unused group
__device__ float g_inv2[TT * DIMC];   // -0.5*log2(e)/softplus(scale[t,t,d])^2
__device__ float g_v[TT];             // softplus(variance[t,t])

__device__ __forceinline__ float softplus_f(float a) {
    return (a > 20.0f) ? a : log1pf(__expf(a));
}

// ---------------------------------------------------------------------------
// Prep (1 CTA): counting-sort rows by task into 32-row groups + precompute
// all softplus-derived constants. Fully parallel (no serial tid==0 loop).
// ---------------------------------------------------------------------------
__global__ void rbf_prep(const int* __restrict__ i_task,
                         const float* __restrict__ scale_raw,
                         const float* __restrict__ var_raw) {
    __shared__ int cnt[TT];
    __shared__ int base[TT];    // element base per task (multiple of 32)
    __shared__ int gbase[TT];   // group base per task
    __shared__ int ng[TT];      // group count per task
    __shared__ int cur[TT];
    const int tid = threadIdx.x;

    if (tid < TT) { cnt[tid] = 0; cur[tid] = 0; }
    for (int idx = tid; idx < MAXG * TR / 4; idx += blockDim.x)
        ((int4*)g_perm)[idx] = make_int4(-1, -1, -1, -1);

    if (tid < TT * DIMC) {
        const int t = tid / DIMC, d = tid % DIMC;
        const float s = softplus_f(scale_raw[t * (TT * DIMC) + t * DIMC + d]);
        g_inv2[tid] = -0.5f * 1.4426950408889634f / (s * s);  // fold log2(e)
    }
    if (tid < TT) g_v[tid] = softplus_f(var_raw[tid * TT + tid]);
    __syncthreads();

    for (int r = tid; r < NN; r += blockDim.x) atomicAdd(&cnt[i_task[r]], 1);
    __syncthreads();

    if (tid < TT) {
        int eb = 0, gb = 0;
        for (int u = 0; u < tid; u++) {
            const int g = (cnt[u] + TR - 1) / TR;
            gb += g; eb += g * TR;
        }
        base[tid]  = eb;
        gbase[tid] = gb;
        ng[tid]    = (cnt[tid] + TR - 1) / TR;
    }
    __syncthreads();

    if (tid < MAXG) {
        int val = -1;
#pragma unroll
        for (int t = 0; t < TT; t++)
            if (tid >= gbase[t] && tid < gbase[t] + ng[t]) val = t;
        g_gtask[tid] = val;
    }

    for (int r = tid; r < NN; r += blockDim.x) {
        const int t = i_task[r];
        const int p = atomicAdd(&cur[t], 1);
        g_perm[base[t] + p] = r;
    }
}

// ---------------------------------------------------------------------------
// Main: one CTA = 32 rows (same task t) x 128 columns.
//  - x rows gathered ONCE per CTA into transposed smem (kills the 8x-redundant
//    scattered LDG that dominated L1 wavefronts)
//  - xx read by broadcast LDG only for matched columns (no smem staging)
//  - ballot -> warp-uniform match mask; compute only ~1/8 of columns
//  - padded smem tile staging -> coalesced 512B row-segment STG.128
// ---------------------------------------------------------------------------
__global__ __launch_bounds__(256) void rbf_main(
    const float* __restrict__ x,
    const float* __restrict__ xx,
    const int*  __restrict__ ii,
    float* __restrict__ out)
{
    const int g = blockIdx.y;
    const int t = g_gtask[g];
    if (t < 0) return;

    const int c0   = blockIdx.x * TC;
    const int tid  = threadIdx.x;
    const int lane = tid & 31;
    const int w    = tid >> 5;

    __shared__ int   s_ii[TC];
    __shared__ int   s_rows[TR];
    __shared__ float s_xT[DIMC * XT_STRIDE];   // x transposed: [d][row], stride 33
    __shared__ float tile[TR * TILE_STRIDE];   // 16.9 KB staging

    if (tid < TC) s_ii[tid] = ii[c0 + tid];

    // Gather the 32 x-rows once: thread (r,d) with r=tid>>3, d=tid&7.
    {
        const int r = tid >> 3;          // 0..31
        const int d = tid & 7;           // 0..7
        const int row = g_perm[g * TR + r];   // 8 threads broadcast-load same addr
        if (d == 0) s_rows[r] = row;
        s_xT[d * XT_STRIDE + r] = (row >= 0) ? x[row * DIMC + d] : 0.0f;
    }

    // zero-fill staging tile (values overwrite matched cells later)
    const float4 z4 = make_float4(0.f, 0.f, 0.f, 0.f);
    for (int idx = tid; idx < TR * TILE_STRIDE / 4; idx += 256)
        ((float4*)tile)[idx] = z4;

    // per-task constants (precomputed by prep)
    float inv2[DIMC];
    {
        const float4 a = *(const float4*)&g_inv2[t * DIMC + 0];
        const float4 b = *(const float4*)&g_inv2[t * DIMC + 4];
        inv2[0] = a.x; inv2[1] = a.y; inv2[2] = a.z; inv2[3] = a.w;
        inv2[4] = b.x; inv2[5] = b.y; inv2[6] = b.z; inv2[7] = b.w;
    }
    const float v = g_v[t];

    __syncthreads();

    // lane = row
    const bool valid = (s_rows[lane] >= 0);
    float xr[DIMC];
#pragma unroll
    for (int d = 0; d < DIMC; d++) xr[d] = s_xT[d * XT_STRIDE + lane];  // conflict-free

    // warp-uniform 16-bit match mask for this warp's 16 columns
    const int cchk = w * 16 + (lane & 15);
    unsigned mask = __ballot_sync(0xffffffffu, (s_ii[cchk] == t) && (lane < 16));

    while (mask) {
        const int k = __ffs(mask) - 1;
        mask &= mask - 1;
        const int c = w * 16 + k;
        // broadcast LDG: all lanes same address (1 sector), L2-hot across groups
        const float4 xa = __ldg((const float4*)&xx[(c0 + c) * DIMC + 0]);
        const float4 xb = __ldg((const float4*)&xx[(c0 + c) * DIMC + 4]);
        float sum;
        float d0 = xr[0] - xa.x; sum = d0 * d0 * inv2[0];
        float d1 = xr[1] - xa.y; sum = fmaf(d1 * d1, inv2[1], sum);
        float d2 = xr[2] - xa.z; sum = fmaf(d2 * d2, inv2[2], sum);
        float d3 = xr[3] - xa.w; sum = fmaf(d3 * d3, inv2[3], sum);
        float d4 = xr[4] - xb.x; sum = fmaf(d4 * d4, inv2[4], sum);
        float d5 = xr[5] - xb.y; sum = fmaf(d5 * d5, inv2[5], sum);
        float d6 = xr[6] - xb.z; sum = fmaf(d6 * d6, inv2[6], sum);
        float d7 = xr[7] - xb.w; sum = fmaf(d7 * d7, inv2[7], sum);
        const float val = exp2f(sum) * v;     // log2(e) folded into inv2
        if (valid) tile[lane * TILE_STRIDE + c] = val;
    }

    __syncthreads();

    // write phase: warp w writes rows 4w..4w+3, 512B coalesced each
#pragma unroll
    for (int rr = 0; rr < 4; rr++) {
        const int r = w * 4 + rr;
        const int row = s_rows[r];
        if (row >= 0) {
            const float4 vv = *(const float4*)&tile[r * TILE_STRIDE + lane * 4];
            *(float4*)&out[(long)row * MM + c0 + lane * 4] = vv;
        }
    }
}

// ---------------------------------------------------------------------------
extern "C" void kernel_launch(void* const* d_in, const int* in_sizes, int n_in,
                              void* d_out, int out_size)
{
    const float* x     = (const float*)d_in[0];
    const float* xx    = (const float*)d_in[1];
    const float* scale = (const float*)d_in[2];
    const float* var   = (const float*)d_in[3];
    const int*   i_t   = (const int*)d_in[4];
    const int*   ii_t  = (const int*)d_in[5];
    float* out = (float*)d_out;

    rbf_prep<<<1, 256>>>(i_t, scale, var);

    dim3 grid(MM / TC, MAXG);
    rbf_main<<<grid, 256>>>(x, xx, ii_t, out);
}

// round 4
// speedup vs baseline: 1.1858x; 1.1858x over previous
#include <cuda_runtime.h>
#include <cuda_bf16.h>
#include <cstdint>

// Problem shape (fixed by the dataset): N=M=4096, DIM=8, TASKS=8
constexpr int NN   = 4096;
constexpr int MM   = 4096;
constexpr int DIMC = 8;
constexpr int TT   = 8;

constexpr int TR = 32;    // rows per group (== warp size)
constexpr int TC = 128;   // columns per tile
constexpr int TILE_STRIDE = 132;   // padded smem stride (write-phase conflict-free)
constexpr int XT_STRIDE   = 33;    // transposed-x stride (conflict-free reads)
constexpr int MAXG = 136;          // >= floor(4096/32) + (TASKS-1) = 135

// Scratch (no cudaMalloc allowed)
__device__ int   g_perm[MAXG * TR];   // row indices grouped by task, -1 = pad
__device__ int   g_gtask[MAXG];       // task id per group, -1 = unused group
__device__ float g_inv2[TT * DIMC];   // -0.5*log2(e)/softplus(scale[t,t,d])^2
__device__ float g_v[TT];             // softplus(variance[t,t])

__device__ __forceinline__ float softplus_f(float a) {
    return (a > 20.0f) ? a : log1pf(__expf(a));
}

// ---------------------------------------------------------------------------
// Prep (1 CTA, 1024 threads): counting-sort rows by task into 32-row groups.
// Warp-aggregated atomics: one smem atomic per (warp, task) instead of one
// per element (kills the 32-cyc/warp same-bank ATOMS serialization).
// ---------------------------------------------------------------------------
__global__ __launch_bounds__(1024) void rbf_prep(
    const int* __restrict__ i_task,
    const float* __restrict__ scale_raw,
    const float* __restrict__ var_raw)
{
    __shared__ int cnt[TT];
    __shared__ int base[TT];    // element base per task (multiple of 32)
    __shared__ int gbase[TT];   // group base per task
    __shared__ int ngr[TT];     // group count per task
    __shared__ int cur[TT];
    const int tid  = threadIdx.x;
    const int lane = tid & 31;

    if (tid < TT) { cnt[tid] = 0; cur[tid] = 0; }
    for (int idx = tid; idx < MAXG * TR / 4; idx += 1024)
        ((int4*)g_perm)[idx] = make_int4(-1, -1, -1, -1);

    if (tid < TT * DIMC) {
        const int t = tid / DIMC, d = tid % DIMC;
        const float s = softplus_f(scale_raw[t * (TT * DIMC) + t * DIMC + d]);
        g_inv2[tid] = -0.5f * 1.4426950408889634f / (s * s);  // fold log2(e)
    }
    if (tid < TT) g_v[tid] = softplus_f(var_raw[tid * TT + tid]);
    __syncthreads();

    // ---- counting pass (warp-aggregated) ----
    int myt[NN / 1024];
#pragma unroll
    for (int j = 0; j < NN / 1024; j++) {
        const int t = i_task[tid + 1024 * j];
        myt[j] = t;
#pragma unroll
        for (int u = 0; u < TT; u++) {
            const unsigned m = __ballot_sync(0xffffffffu, t == u);
            if (m && lane == 0) atomicAdd(&cnt[u], __popc(m));
        }
    }
    __syncthreads();

    if (tid < TT) {
        int eb = 0, gb = 0;
        for (int u = 0; u < tid; u++) {
            const int g = (cnt[u] + TR - 1) / TR;
            gb += g; eb += g * TR;
        }
        base[tid]  = eb;
        gbase[tid] = gb;
        ngr[tid]   = (cnt[tid] + TR - 1) / TR;
    }
    __syncthreads();

    if (tid < MAXG) {
        int val = -1;
#pragma unroll
        for (int t = 0; t < TT; t++)
            if (tid >= gbase[t] && tid < gbase[t] + ngr[t]) val = t;
        g_gtask[tid] = val;
    }

    // ---- scatter pass (warp-aggregated) ----
#pragma unroll
    for (int j = 0; j < NN / 1024; j++) {
        const int r = tid + 1024 * j;
        const int t = myt[j];
#pragma unroll
        for (int u = 0; u < TT; u++) {
            const unsigned m = __ballot_sync(0xffffffffu, t == u);
            if (m) {
                const int leader = __ffs(m) - 1;
                int b = 0;
                if (lane == leader) b = atomicAdd(&cur[u], __popc(m));
                b = __shfl_sync(0xffffffffu, b, leader);
                if (t == u)
                    g_perm[base[u] + b + __popc(m & ((1u << lane) - 1u))] = r;
            }
        }
    }
}

// ---------------------------------------------------------------------------
// Main: one CTA = 32 rows (same task t) x 128 columns.
//  - x rows gathered ONCE per CTA into transposed smem (no 8x-redundant LDG)
//  - xx tile prefetched into smem; inner loop is LDS broadcast (low latency)
//  - ballot -> warp-uniform match mask; compute only ~1/8 of columns
//  - padded smem tile staging -> coalesced 512B row-segment STG.128
// ---------------------------------------------------------------------------
__global__ __launch_bounds__(256) void rbf_main(
    const float* __restrict__ x,
    const float* __restrict__ xx,
    const int*  __restrict__ ii,
    float* __restrict__ out)
{
    const int g = blockIdx.y;
    const int t = g_gtask[g];
    if (t < 0) return;

    const int c0   = blockIdx.x * TC;
    const int tid  = threadIdx.x;
    const int lane = tid & 31;
    const int w    = tid >> 5;

    __shared__ int   s_ii[TC];
    __shared__ int   s_rows[TR];
    __shared__ float s_xx[TC * DIMC];          // 4 KB, prefetched
    __shared__ float s_xT[DIMC * XT_STRIDE];   // x transposed [d][row]
    __shared__ float tile[TR * TILE_STRIDE];   // 16.9 KB staging

    if (tid < TC) s_ii[tid] = ii[c0 + tid];
    // xx tile: 1024 floats, one float4 per thread, coalesced
    ((float4*)s_xx)[tid] = ((const float4*)(xx + c0 * DIMC))[tid];

    // Gather the 32 x-rows once: thread (r,d) with r=tid>>3, d=tid&7
    {
        const int r = tid >> 3;
        const int d = tid & 7;
        const int row = g_perm[g * TR + r];    // 8 threads broadcast same addr
        if (d == 0) s_rows[r] = row;
        s_xT[d * XT_STRIDE + r] = (row >= 0) ? x[row * DIMC + d] : 0.0f;
    }

    // zero-fill staging tile
    const float4 z4 = make_float4(0.f, 0.f, 0.f, 0.f);
    for (int idx = tid; idx < TR * TILE_STRIDE / 4; idx += 256)
        ((float4*)tile)[idx] = z4;

    // per-task constants (precomputed by prep)
    float inv2[DIMC];
    {
        const float4 a = *(const float4*)&g_inv2[t * DIMC + 0];
        const float4 b = *(const float4*)&g_inv2[t * DIMC + 4];
        inv2[0] = a.x; inv2[1] = a.y; inv2[2] = a.z; inv2[3] = a.w;
        inv2[4] = b.x; inv2[5] = b.y; inv2[6] = b.z; inv2[7] = b.w;
    }
    const float v = g_v[t];

    __syncthreads();

    // lane = row; conflict-free reads from transposed x
    const bool valid = (s_rows[lane] >= 0);
    float xr[DIMC];
#pragma unroll
    for (int d = 0; d < DIMC; d++) xr[d] = s_xT[d * XT_STRIDE + lane];

    // warp-uniform 16-bit match mask for this warp's 16 columns
    const int cchk = w * 16 + (lane & 15);
    unsigned mask = __ballot_sync(0xffffffffu, (s_ii[cchk] == t) && (lane < 16));

    while (mask) {
        const int k = __ffs(mask) - 1;
        mask &= mask - 1;
        const int c = w * 16 + k;
        const float4 xa = *(const float4*)&s_xx[c * DIMC + 0];  // LDS broadcast
        const float4 xb = *(const float4*)&s_xx[c * DIMC + 4];
        float sum;
        float d0 = xr[0] - xa.x; sum = d0 * d0 * inv2[0];
        float d1 = xr[1] - xa.y; sum = fmaf(d1 * d1, inv2[1], sum);
        float d2 = xr[2] - xa.z; sum = fmaf(d2 * d2, inv2[2], sum);
        float d3 = xr[3] - xa.w; sum = fmaf(d3 * d3, inv2[3], sum);
        float d4 = xr[4] - xb.x; sum = fmaf(d4 * d4, inv2[4], sum);
        float d5 = xr[5] - xb.y; sum = fmaf(d5 * d5, inv2[5], sum);
        float d6 = xr[6] - xb.z; sum = fmaf(d6 * d6, inv2[6], sum);
        float d7 = xr[7] - xb.w; sum = fmaf(d7 * d7, inv2[7], sum);
        const float val = exp2f(sum) * v;     // log2(e) folded into inv2
        if (valid) tile[lane * TILE_STRIDE + c] = val;
    }

    __syncthreads();

    // write phase: warp w writes rows 4w..4w+3, 512B coalesced each
#pragma unroll
    for (int rr = 0; rr < 4; rr++) {
        const int r = w * 4 + rr;
        const int row = s_rows[r];
        if (row >= 0) {
            const float4 vv = *(const float4*)&tile[r * TILE_STRIDE + lane * 4];
            *(float4*)&out[(long)row * MM + c0 + lane * 4] = vv;
        }
    }
}

// ---------------------------------------------------------------------------
extern "C" void kernel_launch(void* const* d_in, const int* in_sizes, int n_in,
                              void* d_out, int out_size)
{
    const float* x     = (const float*)d_in[0];
    const float* xx    = (const float*)d_in[1];
    const float* scale = (const float*)d_in[2];
    const float* var   = (const float*)d_in[3];
    const int*   i_t   = (const int*)d_in[4];
    const int*   ii_t  = (const int*)d_in[5];
    float* out = (float*)d_out;

    rbf_prep<<<1, 1024>>>(i_t, scale, var);

    dim3 grid(MM / TC, MAXG);
    rbf_main<<<grid, 256>>>(x, xx, ii_t, out);
}

// round 5
// speedup vs baseline: 1.5979x; 1.3476x over previous
#include <cuda_runtime.h>
#include <cuda_bf16.h>
#include <cstdint>

// Problem shape (fixed by the dataset): N=M=4096, DIM=8, TASKS=8
constexpr int NN   = 4096;
constexpr int MM   = 4096;
constexpr int DIMC = 8;
constexpr int TT   = 8;

constexpr int TR = 32;    // rows per group (== warp size)
constexpr int TC = 128;   // columns per tile
constexpr int TILE_STRIDE = 132;   // padded smem stride (write-phase conflict-free)
constexpr int XT_STRIDE   = 33;    // transposed-x stride (conflict-free reads)
constexpr int MAXG = 136;          // >= floor(4096/32) + (TASKS-1) = 135
constexpr int NCHUNK = NN / 32;    // 128 warp-chunks of 32 elements

// Scratch (no cudaMalloc allowed)
__device__ int   g_perm[MAXG * TR];   // row indices grouped by task, -1 = pad
__device__ int   g_gtask[MAXG];       // task id per group, -1 = unused group
__device__ float g_inv2[TT * DIMC];   // -0.5*log2(e)/softplus(scale[t,t,d])^2
__device__ float g_v[TT];             // softplus(variance[t,t])

__device__ __forceinline__ float softplus_f(float a) {
    return (a > 20.0f) ? a : log1pf(__expf(a));
}

// ---------------------------------------------------------------------------
// Prep (1 CTA, 1024 threads): ATOMIC-FREE counting sort of rows by task.
// ballot counts per 32-elem chunk -> smem scan across 128 chunks -> each
// element computes its slot directly. No atomic latency chains.
// Element r = j*1024 + wid*32 + lane  ->  chunk = j*32 + wid (monotone in r).
// ---------------------------------------------------------------------------
__global__ __launch_bounds__(1024) void rbf_prep(
    const int* __restrict__ i_task,
    const float* __restrict__ scale_raw,
    const float* __restrict__ var_raw)
{
    __shared__ int s_scan[TT][NCHUNK];  // per-task per-chunk counts -> inclusive scan
    __shared__ int s_excl[TT][NCHUNK];  // exclusive chunk prefix per task
    __shared__ int s_tot[TT];
    __shared__ int base[TT];            // element base per task (multiple of 32)
    __shared__ int gbase[TT];           // group base per task
    __shared__ int ngr[TT];             // group count per task

    const int tid  = threadIdx.x;
    const int lane = tid & 31;
    const int wid  = tid >> 5;          // 0..31

    for (int idx = tid; idx < MAXG * TR / 4; idx += 1024)
        ((int4*)g_perm)[idx] = make_int4(-1, -1, -1, -1);

    if (tid < TT * DIMC) {
        const int t = tid / DIMC, d = tid % DIMC;
        const float s = softplus_f(scale_raw[t * (TT * DIMC) + t * DIMC + d]);
        g_inv2[tid] = -0.5f * 1.4426950408889634f / (s * s);  // fold log2(e)
    }
    if (tid < TT) g_v[tid] = softplus_f(var_raw[tid * TT + tid]);

    // ---- pass 1: per-chunk ballot counts + own rank-in-chunk ----
    int myt[NN / 1024];
    int myrank[NN / 1024];
#pragma unroll
    for (int j = 0; j < NN / 1024; j++) {
        const int t = i_task[j * 1024 + tid];
        myt[j] = t;
        const int chunk = j * 32 + wid;
        unsigned m_own = 0;
#pragma unroll
        for (int u = 0; u < TT; u++) {
            const unsigned m = __ballot_sync(0xffffffffu, t == u);
            if (lane == u) s_scan[u][chunk] = __popc(m);   // lane u stores count
            if (t == u) m_own = m;
        }
        myrank[j] = __popc(m_own & ((1u << lane) - 1u));
    }
    __syncthreads();

    // ---- pass 2: Hillis-Steele inclusive scan over 128 chunks per task ----
    {
        const int u = tid >> 7;         // 0..7
        const int c = tid & 127;        // 0..127
        const int orig = s_scan[u][c];
#pragma unroll
        for (int off = 1; off < NCHUNK; off <<= 1) {
            const int add = (c >= off) ? s_scan[u][c - off] : 0;
            __syncthreads();
            s_scan[u][c] += add;
            __syncthreads();
        }
        s_excl[u][c] = s_scan[u][c] - orig;
        if (c == NCHUNK - 1) s_tot[u] = s_scan[u][c];
    }
    __syncthreads();

    // ---- pass 3: per-task bases + group table ----
    if (tid < TT) {
        int eb = 0, gb = 0;
        for (int v = 0; v < tid; v++) {
            const int g = (s_tot[v] + TR - 1) / TR;
            gb += g; eb += g * TR;
        }
        base[tid]  = eb;
        gbase[tid] = gb;
        ngr[tid]   = (s_tot[tid] + TR - 1) / TR;
    }
    __syncthreads();

    if (tid < MAXG) {
        int val = -1;
#pragma unroll
        for (int t = 0; t < TT; t++)
            if (tid >= gbase[t] && tid < gbase[t] + ngr[t]) val = t;
        g_gtask[tid] = val;
    }

    // ---- pass 4: direct scatter, no atomics ----
#pragma unroll
    for (int j = 0; j < NN / 1024; j++) {
        const int r = j * 1024 + tid;
        const int t = myt[j];
        const int chunk = j * 32 + wid;
        g_perm[base[t] + s_excl[t][chunk] + myrank[j]] = r;
    }
}

// ---------------------------------------------------------------------------
// Main: one CTA = 32 rows (same task t) x 128 columns.
//  - x rows gathered ONCE per CTA into transposed smem
//  - xx tile prefetched into smem; compute reads are LDS broadcast
//  - warp-uniform match mask; unmatched columns produce 0 with ~2 instr
//  - per-warp register float4 blocks -> STS.128 (NO separate zero-fill pass)
//  - coalesced 512B row-segment STG.128 out of the tile
// ---------------------------------------------------------------------------
__global__ __launch_bounds__(256) void rbf_main(
    const float* __restrict__ x,
    const float* __restrict__ xx,
    const int*  __restrict__ ii,
    float* __restrict__ out)
{
    const int g = blockIdx.y;
    const int t = g_gtask[g];
    if (t < 0) return;

    const int c0   = blockIdx.x * TC;
    const int tid  = threadIdx.x;
    const int lane = tid & 31;
    const int w    = tid >> 5;

    __shared__ int   s_ii[TC];
    __shared__ int   s_rows[TR];
    __shared__ float s_xx[TC * DIMC];          // 4 KB, prefetched
    __shared__ float s_xT[DIMC * XT_STRIDE];   // x transposed [d][row]
    __shared__ float tile[TR * TILE_STRIDE];   // 16.9 KB staging

    if (tid < TC) s_ii[tid] = ii[c0 + tid];
    // xx tile: 1024 floats, one float4 per thread, coalesced
    ((float4*)s_xx)[tid] = ((const float4*)(xx + c0 * DIMC))[tid];

    // Gather the 32 x-rows once: thread (r,d) with r=tid>>3, d=tid&7
    {
        const int r = tid >> 3;
        const int d = tid & 7;
        const int row = g_perm[g * TR + r];    // 8 threads broadcast same addr
        if (d == 0) s_rows[r] = row;
        s_xT[d * XT_STRIDE + r] = (row >= 0) ? x[row * DIMC + d] : 0.0f;
    }

    // per-task constants (precomputed by prep)
    float inv2[DIMC];
    {
        const float4 a = *(const float4*)&g_inv2[t * DIMC + 0];
        const float4 b = *(const float4*)&g_inv2[t * DIMC + 4];
        inv2[0] = a.x; inv2[1] = a.y; inv2[2] = a.z; inv2[3] = a.w;
        inv2[4] = b.x; inv2[5] = b.y; inv2[6] = b.z; inv2[7] = b.w;
    }
    const float v = g_v[t];

    __syncthreads();

    // lane = row; conflict-free reads from transposed x
    float xr[DIMC];
#pragma unroll
    for (int d = 0; d < DIMC; d++) xr[d] = s_xT[d * XT_STRIDE + lane];

    // warp-uniform 16-bit match mask for this warp's 16 columns
    const int cchk = w * 16 + (lane & 15);
    const unsigned mask = __ballot_sync(0xffffffffu, (s_ii[cchk] == t) && (lane < 16));

    // compute all 16 columns as 4 register float4 blocks -> STS.128
#pragma unroll
    for (int q = 0; q < 4; q++) {
        float vr[4];
#pragma unroll
        for (int k = 0; k < 4; k++) {
            float val = 0.0f;
            if ((mask >> (q * 4 + k)) & 1u) {        // warp-uniform branch
                const int c = w * 16 + q * 4 + k;
                const float4 xa = *(const float4*)&s_xx[c * DIMC + 0];  // broadcast
                const float4 xb = *(const float4*)&s_xx[c * DIMC + 4];
                float sum;
                float d0 = xr[0] - xa.x; sum = d0 * d0 * inv2[0];
                float d1 = xr[1] - xa.y; sum = fmaf(d1 * d1, inv2[1], sum);
                float d2 = xr[2] - xa.z; sum = fmaf(d2 * d2, inv2[2], sum);
                float d3 = xr[3] - xa.w; sum = fmaf(d3 * d3, inv2[3], sum);
                float d4 = xr[4] - xb.x; sum = fmaf(d4 * d4, inv2[4], sum);
                float d5 = xr[5] - xb.y; sum = fmaf(d5 * d5, inv2[5], sum);
                float d6 = xr[6] - xb.z; sum = fmaf(d6 * d6, inv2[6], sum);
                float d7 = xr[7] - xb.w; sum = fmaf(d7 * d7, inv2[7], sum);
                val = exp2f(sum) * v;                // log2(e) folded into inv2
            }
            vr[k] = val;
        }
        // STS.128: first-word bank = (4*lane + w*16 + q*4) % 32 -> conflict-free
        *(float4*)&tile[lane * TILE_STRIDE + w * 16 + q * 4] =
            make_float4(vr[0], vr[1], vr[2], vr[3]);
    }

    __syncthreads();

    // write phase: warp w writes rows 4w..4w+3, 512B coalesced each
#pragma unroll
    for (int rr = 0; rr < 4; rr++) {
        const int r = w * 4 + rr;
        const int row = s_rows[r];
        if (row >= 0) {
            const float4 vv = *(const float4*)&tile[r * TILE_STRIDE + lane * 4];
            *(float4*)&out[(long)row * MM + c0 + lane * 4] = vv;
        }
    }
}

// ---------------------------------------------------------------------------
extern "C" void kernel_launch(void* const* d_in, const int* in_sizes, int n_in,
                              void* d_out, int out_size)
{
    const float* x     = (const float*)d_in[0];
    const float* xx    = (const float*)d_in[1];
    const float* scale = (const float*)d_in[2];
    const float* var   = (const float*)d_in[3];
    const int*   i_t   = (const int*)d_in[4];
    const int*   ii_t  = (const int*)d_in[5];
    float* out = (float*)d_out;

    rbf_prep<<<1, 1024>>>(i_t, scale, var);

    dim3 grid(MM / TC, MAXG);
    rbf_main<<<grid, 256>>>(x, xx, ii_t, out);
}

// round 7
// speedup vs baseline: 1.7135x; 1.0723x over previous
#include <cuda_runtime.h>
#include <cuda_bf16.h>
#include <cstdint>

// Problem shape (fixed by the dataset): N=M=4096, DIM=8, TASKS=8
constexpr int NN   = 4096;
constexpr int MM   = 4096;
constexpr int DIMC = 8;
constexpr int TT   = 8;

constexpr int TR = 32;     // rows per group (== warp size)
constexpr int TC = 128;    // columns per tile
constexpr int TC_STRIDE = 129;  // compact-tile stride (odd -> conflict-free STS)
constexpr int XT_STRIDE = 33;   // transposed-x stride
constexpr int MAXG = 136;       // >= floor(4096/32) + (TASKS-1) = 135
constexpr int NCHUNK = 128;     // warp-chunks of 32 elements in prep
constexpr int CNT_S  = 129;     // prep count-array stride

// Scratch (no cudaMalloc allowed)
__device__ int   g_perm[MAXG * TR];   // row indices grouped by task, -1 = pad
__device__ int   g_gtask[MAXG];       // task id per group, -1 = unused group
__device__ float g_inv2[TT * DIMC];   // -0.5*log2(e)/softplus(scale[t,t,d])^2
__device__ float g_v[TT];             // softplus(variance[t,t])

__device__ __forceinline__ float softplus_f(float a) {
    return (a > 20.0f) ? a : log1pf(__expf(a));
}

// ---------------------------------------------------------------------------
// Prep (1 CTA, 1024 threads): atomic-free counting sort, shfl warp-scan
// (2 barriers in the scan instead of 14), pad-only g_perm init.
// ---------------------------------------------------------------------------
__global__ __launch_bounds__(1024) void rbf_prep(
    const int* __restrict__ i_task,
    const float* __restrict__ scale_raw,
    const float* __restrict__ var_raw)
{
    __shared__ int s_cnt[TT * CNT_S];   // per-task per-chunk counts
    __shared__ int s_excl[TT * CNT_S];  // exclusive chunk prefix per task
    __shared__ int s_wt[TT][4];         // warp totals for the 128-wide scan
    __shared__ int s_tot[TT];
    __shared__ int base[TT];            // element base per task (multiple of 32)
    __shared__ int gbase[TT];           // group base per task
    __shared__ int ngr[TT];             // group count per task

    const int tid  = threadIdx.x;
    const int lane = tid & 31;
    const int wid  = tid >> 5;          // 0..31

    if (tid < TT * DIMC) {
        const int t = tid / DIMC, d = tid % DIMC;
        const float s = softplus_f(scale_raw[t * (TT * DIMC) + t * DIMC + d]);
        g_inv2[tid] = -0.5f * 1.4426950408889634f / (s * s);  // fold log2(e)
    }
    if (tid < TT) g_v[tid] = softplus_f(var_raw[tid * TT + tid]);

    // ---- pass 1: per-chunk ballot counts + own rank-in-chunk ----
    int myt[NN / 1024];
    int myrank[NN / 1024];
#pragma unroll
    for (int j = 0; j < NN / 1024; j++) {
        const int t = i_task[j * 1024 + tid];
        myt[j] = t;
        const int chunk = j * 32 + wid;
        unsigned m_own = 0;
#pragma unroll
        for (int u = 0; u < TT; u++) {
            const unsigned m = __ballot_sync(0xffffffffu, t == u);
            if (lane == u) s_cnt[u * CNT_S + chunk] = __popc(m);
            if (t == u) m_own = m;
        }
        myrank[j] = __popc(m_own & ((1u << lane) - 1u));
    }
    __syncthreads();

    // ---- pass 2: 128-wide scan per task via shfl warp-scan ----
    {
        const int u = tid >> 7;         // 0..7 (constant within each warp)
        const int c = tid & 127;        // 0..127
        const int wir = c >> 5;         // warp index within the 128-row
        const int orig = s_cnt[u * CNT_S + c];
        int v = orig;
#pragma unroll
        for (int off = 1; off < 32; off <<= 1) {
            const int tv = __shfl_up_sync(0xffffffffu, v, off);
            if (lane >= off) v += tv;
        }
        if (lane == 31) s_wt[u][wir] = v;
        __syncthreads();
        int add = 0;
#pragma unroll
        for (int j2 = 0; j2 < 3; j2++) if (wir > j2) add += s_wt[u][j2];
        s_excl[u * CNT_S + c] = v + add - orig;
        if (c == 127) s_tot[u] = v + add;
    }
    __syncthreads();

    // ---- pass 3: per-task bases + group table ----
    if (tid < TT) {
        int eb = 0, gb = 0;
        for (int u = 0; u < tid; u++) {
            const int g = (s_tot[u] + TR - 1) / TR;
            gb += g; eb += g * TR;
        }
        base[tid]  = eb;
        gbase[tid] = gb;
        ngr[tid]   = (s_tot[tid] + TR - 1) / TR;
    }
    __syncthreads();

    if (tid < MAXG) {
        int val = -1;
#pragma unroll
        for (int t = 0; t < TT; t++)
            if (tid >= gbase[t] && tid < gbase[t] + ngr[t]) val = t;
        g_gtask[tid] = val;
    }

    // pad-only init: at most 31 slots per task
    if (tid < TT * TR) {
        const int tt = tid >> 5, k = tid & 31;
        const int c = s_tot[tt];
        if (k < ngr[tt] * TR - c) g_perm[base[tt] + c + k] = -1;
    }

    // ---- pass 4: direct scatter, no atomics ----
#pragma unroll
    for (int j = 0; j < NN / 1024; j++) {
        const int r = j * 1024 + tid;
        const int t = myt[j];
        const int chunk = j * 32 + wid;
        g_perm[base[t] + s_excl[t * CNT_S + chunk] + myrank[j]] = r;
    }
}

// ---------------------------------------------------------------------------
// Main: one CTA = 32 rows (same task t) x 128 columns.
//  - ballot-built column compaction (CNT matched cols, ~16)
//  - compute stores ONLY matched values to a compact smem tile (~2KB, was 16.5KB)
//  - write phase assembles zeros + gathered values in registers -> STG.128
// ---------------------------------------------------------------------------
__global__ __launch_bounds__(256) void rbf_main(
    const float* __restrict__ x,
    const float* __restrict__ xx,
    const int*  __restrict__ ii,
    float* __restrict__ out)
{
    const int g = blockIdx.y;
    const int t = g_gtask[g];
    if (t < 0) return;

    const int c0   = blockIdx.x * TC;
    const int tid  = threadIdx.x;
    const int lane = tid & 31;
    const int w    = tid >> 5;

    __shared__ int   s_midx[TC];               // col -> compact idx or -1
    __shared__ int   s_mcol[TC];               // compact idx -> col
    __shared__ int   s_wcnt[4];
    __shared__ int   s_rows[TR];
    __shared__ float s_xT[DIMC * XT_STRIDE];   // x transposed [d][row]
    __shared__ float s_xc[TC * DIMC];          // compact xx rows, stride 8
    __shared__ float s_tc[TR * TC_STRIDE];     // compact values [row][m]

    // match eval (warps 0-3) + x gather (all threads) in parallel
    bool match = false;
    if (tid < TC) match = (ii[c0 + tid] == t);
    const unsigned bal = __ballot_sync(0xffffffffu, match);
    if (tid < TC && lane == 0) s_wcnt[w] = __popc(bal);

    {
        const int r = tid >> 3;                // 0..31
        const int d = tid & 7;                 // 0..7
        const int row = g_perm[g * TR + r];    // 8 threads broadcast same addr
        if (d == 0) s_rows[r] = row;
        s_xT[d * XT_STRIDE + r] = (row >= 0) ? x[row * DIMC + d] : 0.0f;
    }

    // per-task constants (precomputed by prep)
    float inv2[DIMC];
    {
        const float4 a = *(const float4*)&g_inv2[t * DIMC + 0];
        const float4 b = *(const float4*)&g_inv2[t * DIMC + 4];
        inv2[0] = a.x; inv2[1] = a.y; inv2[2] = a.z; inv2[3] = a.w;
        inv2[4] = b.x; inv2[5] = b.y; inv2[6] = b.z; inv2[7] = b.w;
    }
    const float v = g_v[t];

    __syncthreads();  // s_wcnt ready

    const int b0 = s_wcnt[0], b1 = s_wcnt[1], b2 = s_wcnt[2], b3 = s_wcnt[3];
    const int CNT = b0 + b1 + b2 + b3;
    if (tid < TC) {
        const int basew = (w >= 1 ? b0 : 0) + (w >= 2 ? b1 : 0) + (w >= 3 ? b2 : 0);
        const int midx = match ? basew + __popc(bal & ((1u << lane) - 1u)) : -1;
        s_midx[tid] = midx;
        if (match) s_mcol[midx] = tid;
    }
    __syncthreads();  // s_mcol/s_midx ready

    // gather xx rows for matched columns only (CNT*32B instead of 4KB)
    {
        const int d = tid & 7;
        for (int m = tid >> 3; m < CNT; m += 32)
            s_xc[m * DIMC + d] = xx[(c0 + s_mcol[m]) * DIMC + d];
    }
    __syncthreads();  // s_xc ready

    // compute: lanes = rows, warp w handles compact cols m = w, w+8, ...
    if (CNT > 0) {
        float xr[DIMC];
#pragma unroll
        for (int d = 0; d < DIMC; d++) xr[d] = s_xT[d * XT_STRIDE + lane];

        for (int m = w; m < CNT; m += 8) {
            const float4 xa = *(const float4*)&s_xc[m * DIMC + 0];  // broadcast
            const float4 xb = *(const float4*)&s_xc[m * DIMC + 4];
            float sum;
            float d0 = xr[0] - xa.x; sum = d0 * d0 * inv2[0];
            float d1 = xr[1] - xa.y; sum = fmaf(d1 * d1, inv2[1], sum);
            float d2 = xr[2] - xa.z; sum = fmaf(d2 * d2, inv2[2], sum);
            float d3 = xr[3] - xa.w; sum = fmaf(d3 * d3, inv2[3], sum);
            float d4 = xr[4] - xb.x; sum = fmaf(d4 * d4, inv2[4], sum);
            float d5 = xr[5] - xb.y; sum = fmaf(d5 * d5, inv2[5], sum);
            float d6 = xr[6] - xb.z; sum = fmaf(d6 * d6, inv2[6], sum);
            float d7 = xr[7] - xb.w; sum = fmaf(d7 * d7, inv2[7], sum);
            // banks (lane + m) % 32 -> conflict-free
            s_tc[lane * TC_STRIDE + m] = exp2f(sum) * v;   // log2(e) in inv2
        }
    }
    __syncthreads();  // s_tc ready

    // write phase: warp w -> rows 4w..4w+3; lane -> cols 4*lane..4*lane+3
    const int4 mi = ((const int4*)s_midx)[lane];  // LDS.128, conflict-free
#pragma unroll
    for (int rr = 0; rr < 4; rr++) {
        const int r = w * 4 + rr;
        const int row = s_rows[r];
        if (row >= 0) {
            float4 o = make_float4(0.f, 0.f, 0.f, 0.f);
            const int rb = r * TC_STRIDE;
            if (mi.x >= 0) o.x = s_tc[rb + mi.x];   // distinct midx -> no conflicts
            if (mi.y >= 0) o.y = s_tc[rb + mi.y];
            if (mi.z >= 0) o.z = s_tc[rb + mi.z];
            if (mi.w >= 0) o.w = s_tc[rb + mi.w];
            *(float4*)&out[(long)row * MM + c0 + lane * 4] = o;
        }
    }
}

// ---------------------------------------------------------------------------
extern "C" void kernel_launch(void* const* d_in, const int* in_sizes, int n_in,
                              void* d_out, int out_size)
{
    const float* x     = (const float*)d_in[0];
    const float* xx    = (const float*)d_in[1];
    const float* scale = (const float*)d_in[2];
    const float* var   = (const float*)d_in[3];
    const int*   i_t   = (const int*)d_in[4];
    const int*   ii_t  = (const int*)d_in[5];
    float* out = (float*)d_out;

    rbf_prep<<<1, 1024>>>(i_t, scale, var);

    dim3 grid(MM / TC, MAXG);
    rbf_main<<<grid, 256>>>(x, xx, ii_t, out);
}